// round 3
// baseline (speedup 1.0000x reference)
#include <cuda_runtime.h>

#define NN   100000
#define EE   1600000
#define KDIM 256

// ---------------- scratch (device globals) ----------------
__device__ float g_b0[(size_t)NN * KDIM];   // h0, later reused as z
__device__ float g_b1[(size_t)NN * KDIM];   // t = h0 @ W_enc
__device__ float g_b2[(size_t)NN * KDIM];   // h1
__device__ float g_deg[NN];
__device__ float g_dinv[NN];
__device__ int   g_cnt[NN];
__device__ int   g_rowptr[NN + 1];
__device__ int   g_cursor[NN];
__device__ int   g_src[EE];
__device__ float g_val[EE];
__device__ int   g_is64;

// ---------------- edge-index dtype detection ----------------
// If buffer holds int64 (values < 2^31), every odd int32 word is 0.
__global__ void detect_kernel(const int* __restrict__ ei32, int n_int32) {
    __shared__ int any;
    if (threadIdx.x == 0) any = 0;
    __syncthreads();
    for (int i = threadIdx.x; i < 4096; i += blockDim.x) {
        int pos = 2 * i + 1;
        if (pos < n_int32 && ei32[pos] != 0) any = 1;
    }
    __syncthreads();
    if (threadIdx.x == 0) g_is64 = (any == 0) ? 1 : 0;
}

__device__ __forceinline__ int load_idx(const void* ei, int e, int part, int i) {
    if (g_is64) return (int)((const long long*)ei)[(size_t)part * e + i];
    return ((const int*)ei)[(size_t)part * e + i];
}

// ---------------- graph preprocessing ----------------
__global__ void init_kernel(int n) {
    int i = blockIdx.x * blockDim.x + threadIdx.x;
    if (i < n) { g_deg[i] = 1.0f; g_cnt[i] = 0; }   // self-loop weight 1
}

__global__ void edge_pass(const void* __restrict__ ei,
                          const float* __restrict__ ew, int e) {
    int i = blockIdx.x * blockDim.x + threadIdx.x;
    if (i >= e) return;
    int c = load_idx(ei, e, 1, i);       // col = destination
    if ((unsigned)c >= NN) return;
    atomicAdd(&g_deg[c], ew[i]);
    atomicAdd(&g_cnt[c], 1);
}

__global__ void dinv_kernel(int n) {
    int i = blockIdx.x * blockDim.x + threadIdx.x;
    if (i < n) g_dinv[i] = rsqrtf(g_deg[i]);   // deg >= 1 (self loop)
}

// single-block exclusive scan over g_cnt -> g_rowptr, g_cursor
__global__ void scan_kernel(int n) {
    __shared__ int part[1024];
    int tid = threadIdx.x;
    int chunk = (n + 1023) >> 10;
    int beg = tid * chunk;
    int end = beg + chunk; if (end > n) end = n;
    int s = 0;
    for (int i = beg; i < end; i++) s += g_cnt[i];
    part[tid] = s;
    __syncthreads();
    for (int off = 1; off < 1024; off <<= 1) {
        int v = (tid >= off) ? part[tid - off] : 0;
        __syncthreads();
        part[tid] += v;
        __syncthreads();
    }
    int run = (tid > 0) ? part[tid - 1] : 0;
    for (int i = beg; i < end; i++) {
        g_rowptr[i] = run; g_cursor[i] = run; run += g_cnt[i];
    }
    if (tid == 1023) g_rowptr[n] = part[1023];
}

__global__ void scatter_kernel(const void* __restrict__ ei,
                               const float* __restrict__ ew, int e) {
    int i = blockIdx.x * blockDim.x + threadIdx.x;
    if (i >= e) return;
    int r = load_idx(ei, e, 0, i);
    int c = load_idx(ei, e, 1, i);
    if ((unsigned)r >= NN || (unsigned)c >= NN) return;
    int pos = atomicAdd(&g_cursor[c], 1);
    g_src[pos] = r;
    g_val[pos] = ew[i] * g_dinv[r];
}

// buffer selectors (device-side resolution of __device__ global addresses)
__device__ __forceinline__ float* sel_buf(int s) {
    return s == 0 ? g_b0 : (s == 1 ? g_b1 : g_b2);
}

// ---------------- GEMM: C[M,NCOL] = A[M,256] @ W[256,NCOL] (+bias, opt relu) ----------------
template<int NCOL, bool RELU>
__global__ __launch_bounds__(256)
void gemm64(const float* __restrict__ Ain, const float* __restrict__ W,
            const float* __restrict__ bias, float* __restrict__ Cout,
            int M, int asel, int csel) {
    const float* A = (asel < 0) ? Ain : sel_buf(asel);
    float*       C = (csel < 0) ? Cout : sel_buf(csel);
    const int K = KDIM;
    __shared__ float As[16][68];
    __shared__ float Bs[16][68];
    int tid = threadIdx.x;
    int bm = blockIdx.y * 64;
    int bn = blockIdx.x * 64;
    int ty = tid >> 4;          // 0..15
    int tx = tid & 15;          // 0..15
    int aRow = tid >> 2;        // 0..63
    int aCol = (tid & 3) * 4;   // 0,4,8,12
    int bRow = tid >> 4;        // 0..15
    int bCol = (tid & 15) * 4;  // 0..60

    float acc[4][4] = {};

    for (int k0 = 0; k0 < K; k0 += 16) {
        int gr = bm + aRow;
        float4 av = make_float4(0.f, 0.f, 0.f, 0.f);
        if (gr < M) av = *(const float4*)&A[(size_t)gr * K + k0 + aCol];
        As[aCol + 0][aRow] = av.x;
        As[aCol + 1][aRow] = av.y;
        As[aCol + 2][aRow] = av.z;
        As[aCol + 3][aRow] = av.w;
        float4 bv = *(const float4*)&W[(size_t)(k0 + bRow) * NCOL + bn + bCol];
        *(float4*)&Bs[bRow][bCol] = bv;
        __syncthreads();
        #pragma unroll
        for (int k = 0; k < 16; k++) {
            float4 a4 = *(const float4*)&As[k][ty * 4];
            float4 b4 = *(const float4*)&Bs[k][tx * 4];
            float a[4] = {a4.x, a4.y, a4.z, a4.w};
            float b[4] = {b4.x, b4.y, b4.z, b4.w};
            #pragma unroll
            for (int i = 0; i < 4; i++)
                #pragma unroll
                for (int j = 0; j < 4; j++)
                    acc[i][j] = fmaf(a[i], b[j], acc[i][j]);
        }
        __syncthreads();
    }

    #pragma unroll
    for (int i = 0; i < 4; i++) {
        int r = bm + ty * 4 + i;
        if (r >= M) continue;
        #pragma unroll
        for (int j = 0; j < 4; j++) {
            int cidx = bn + tx * 4 + j;
            float v = acc[i][j];
            if (bias) v += bias[cidx];
            if (RELU) v = fmaxf(v, 0.f);
            C[(size_t)r * NCOL + cidx] = v;
        }
    }
}

// ---------------- SpMM: out[c] = dinv[c]*sum_e val_e*feat[src_e] + dinv[c]^2*feat[c] + bias ---
__global__ __launch_bounds__(256)
void spmm_kernel(const float* __restrict__ bias, int n, int fsel, int osel) {
    const float* feat = sel_buf(fsel);
    float*       out  = sel_buf(osel);
    int warp = (blockIdx.x * blockDim.x + threadIdx.x) >> 5;
    int lane = threadIdx.x & 31;
    if (warp >= n) return;
    int beg = g_rowptr[warp];
    int end = g_rowptr[warp + 1];
    const float4* f4 = (const float4*)feat;
    float4 acc0 = make_float4(0.f, 0.f, 0.f, 0.f);
    float4 acc1 = make_float4(0.f, 0.f, 0.f, 0.f);
    for (int e = beg; e < end; e++) {
        int   r = g_src[e];
        float v = g_val[e];
        float4 a = f4[(size_t)r * 64 + lane];
        float4 b = f4[(size_t)r * 64 + 32 + lane];
        acc0.x = fmaf(v, a.x, acc0.x); acc0.y = fmaf(v, a.y, acc0.y);
        acc0.z = fmaf(v, a.z, acc0.z); acc0.w = fmaf(v, a.w, acc0.w);
        acc1.x = fmaf(v, b.x, acc1.x); acc1.y = fmaf(v, b.y, acc1.y);
        acc1.z = fmaf(v, b.z, acc1.z); acc1.w = fmaf(v, b.w, acc1.w);
    }
    float di = g_dinv[warp];
    float d2 = di * di;
    float4 s0 = f4[(size_t)warp * 64 + lane];
    float4 s1 = f4[(size_t)warp * 64 + 32 + lane];
    float4 o0, o1;
    o0.x = di * acc0.x + d2 * s0.x; o0.y = di * acc0.y + d2 * s0.y;
    o0.z = di * acc0.z + d2 * s0.z; o0.w = di * acc0.w + d2 * s0.w;
    o1.x = di * acc1.x + d2 * s1.x; o1.y = di * acc1.y + d2 * s1.y;
    o1.z = di * acc1.z + d2 * s1.z; o1.w = di * acc1.w + d2 * s1.w;
    if (bias) {
        const float4* b4 = (const float4*)bias;
        float4 c0 = b4[lane], c1 = b4[32 + lane];
        o0.x += c0.x; o0.y += c0.y; o0.z += c0.z; o0.w += c0.w;
        o1.x += c1.x; o1.y += c1.y; o1.z += c1.z; o1.w += c1.w;
    }
    float4* out4 = (float4*)out;
    out4[(size_t)warp * 64 + lane]      = o0;
    out4[(size_t)warp * 64 + 32 + lane] = o1;
}

// ---------------- launch ----------------
extern "C" void kernel_launch(void* const* d_in, const int* in_sizes, int n_in,
                              void* d_out, int out_size) {
    const float* x  = (const float*)d_in[0];
    const void*  ei = d_in[1];
    const float* ew = (const float*)d_in[2];
    const float* wd = (const float*)d_in[3];
    const float* bd = (const float*)d_in[4];
    const float* we = (const float*)d_in[5];
    const float* be = (const float*)d_in[6];
    const float* wm = (const float*)d_in[7];
    const float* bmu = (const float*)d_in[8];
    const float* wl = (const float*)d_in[9];
    const float* bl = (const float*)d_in[10];
    float* out = (float*)d_out;

    const int n = NN;
    const int e = EE;

    // dtype detection + graph preprocessing (shared by all 3 convs)
    detect_kernel<<<1, 1024>>>((const int*)ei, 2 * e);
    init_kernel<<<(n + 255) / 256, 256>>>(n);
    edge_pass<<<(e + 255) / 256, 256>>>(ei, ew, e);
    dinv_kernel<<<(n + 255) / 256, 256>>>(n);
    scan_kernel<<<1, 1024>>>(n);
    scatter_kernel<<<(e + 255) / 256, 256>>>(ei, ew, e);

    dim3 g256(4, (n + 63) / 64);
    dim3 g128(2, (n + 63) / 64);

    // h0 = relu(x @ Wd + bd)            -> g_b0
    gemm64<256, true><<<g256, 256>>>(x, wd, bd, nullptr, n, -1, 0);
    // t = h0 @ We                        -> g_b1
    gemm64<256, false><<<g256, 256>>>(nullptr, we, nullptr, nullptr, n, 0, 1);
    // h1 = A_norm @ t + be               -> g_b2
    int spmm_blocks = (n * 32 + 255) / 256;
    spmm_kernel<<<spmm_blocks, 256>>>(be, n, 1, 2);
    // z = A_norm @ h1                    -> g_b0
    spmm_kernel<<<spmm_blocks, 256>>>(nullptr, n, 2, 0);
    // mu = z @ Wmu + bmu ; logstd = z @ Wls + bls
    gemm64<128, false><<<g128, 256>>>(nullptr, wm, bmu, out, n, 0, -1);
    gemm64<128, false><<<g128, 256>>>(nullptr, wl, bl, out + (size_t)n * 128, n, 0, -1);
}

// round 4
// speedup vs baseline: 1.2899x; 1.2899x over previous
#include <cuda_runtime.h>

#define NN   100000
#define EE   1600000
#define KDIM 256

// ---------------- scratch (device globals) ----------------
__device__ float g_b0[(size_t)NN * KDIM];   // h0, later reused as z
__device__ float g_b1[(size_t)NN * KDIM];   // t = h0 @ W_enc
__device__ float g_b2[(size_t)NN * KDIM];   // h1
__device__ float g_wcat[256 * 256];         // [Wmu | Wlogstd]
__device__ float g_bcat[256];
__device__ float g_deg[NN];
__device__ float g_dinv[NN];
__device__ int   g_cnt[NN];
__device__ int   g_rowptr[NN + 1];
__device__ int   g_cursor[NN];
__device__ int   g_src[EE];
__device__ float g_val[EE];
__device__ int   g_is64;

// ---------------- edge-index dtype detection ----------------
__global__ void detect_kernel(const int* __restrict__ ei32, int n_int32) {
    __shared__ int any;
    if (threadIdx.x == 0) any = 0;
    __syncthreads();
    for (int i = threadIdx.x; i < 4096; i += blockDim.x) {
        int pos = 2 * i + 1;
        if (pos < n_int32 && ei32[pos] != 0) any = 1;
    }
    __syncthreads();
    if (threadIdx.x == 0) g_is64 = (any == 0) ? 1 : 0;
}

__device__ __forceinline__ int load_idx(const void* ei, int e, int part, int i) {
    if (g_is64) return (int)((const long long*)ei)[(size_t)part * e + i];
    return ((const int*)ei)[(size_t)part * e + i];
}

// ---------------- graph preprocessing ----------------
__global__ void init_kernel(int n) {
    int i = blockIdx.x * blockDim.x + threadIdx.x;
    if (i < n) { g_deg[i] = 1.0f; g_cnt[i] = 0; }
}

__global__ void edge_pass(const void* __restrict__ ei,
                          const float* __restrict__ ew, int e) {
    int i = blockIdx.x * blockDim.x + threadIdx.x;
    if (i >= e) return;
    int c = load_idx(ei, e, 1, i);
    if ((unsigned)c >= NN) return;
    atomicAdd(&g_deg[c], ew[i]);
    atomicAdd(&g_cnt[c], 1);
}

__global__ void dinv_kernel(int n) {
    int i = blockIdx.x * blockDim.x + threadIdx.x;
    if (i < n) g_dinv[i] = rsqrtf(g_deg[i]);
}

__global__ void scan_kernel(int n) {
    __shared__ int part[1024];
    int tid = threadIdx.x;
    int chunk = (n + 1023) >> 10;
    int beg = tid * chunk;
    int end = beg + chunk; if (end > n) end = n;
    int s = 0;
    for (int i = beg; i < end; i++) s += g_cnt[i];
    part[tid] = s;
    __syncthreads();
    for (int off = 1; off < 1024; off <<= 1) {
        int v = (tid >= off) ? part[tid - off] : 0;
        __syncthreads();
        part[tid] += v;
        __syncthreads();
    }
    int run = (tid > 0) ? part[tid - 1] : 0;
    for (int i = beg; i < end; i++) {
        g_rowptr[i] = run; g_cursor[i] = run; run += g_cnt[i];
    }
    if (tid == 1023) g_rowptr[n] = part[1023];
}

__global__ void scatter_kernel(const void* __restrict__ ei,
                               const float* __restrict__ ew, int e) {
    int i = blockIdx.x * blockDim.x + threadIdx.x;
    if (i >= e) return;
    int r = load_idx(ei, e, 0, i);
    int c = load_idx(ei, e, 1, i);
    if ((unsigned)r >= NN || (unsigned)c >= NN) return;
    int pos = atomicAdd(&g_cursor[c], 1);
    g_src[pos] = r;
    g_val[pos] = ew[i] * g_dinv[r];
}

__global__ void concat_w(const float* __restrict__ wm, const float* __restrict__ wl,
                         const float* __restrict__ bm_, const float* __restrict__ bl_) {
    int i = blockIdx.x * blockDim.x + threadIdx.x;
    if (i < 256 * 256) {
        int k = i >> 8, nn = i & 255;
        g_wcat[i] = (nn < 128) ? wm[k * 128 + nn] : wl[k * 128 + nn - 128];
    }
    if (i < 256) g_bcat[i] = (i < 128) ? bm_[i] : bl_[i - 128];
}

__device__ __forceinline__ float* sel_buf(int s) {
    return s == 0 ? g_b0 : (s == 1 ? g_b1 : g_b2);
}

// ---------------- tf32 helpers ----------------
__device__ __forceinline__ unsigned f2tf32(float x) {
    unsigned r;
    asm("cvt.rna.tf32.f32 %0, %1;" : "=r"(r) : "f"(x));
    return r;
}
__device__ __forceinline__ void split_tf32(float x, unsigned& hi, unsigned& lo) {
    hi = f2tf32(x);
    float r = x - __uint_as_float(hi);
    lo = f2tf32(r);
}
__device__ __forceinline__ void mma8(float c[4], const unsigned a[4],
                                     unsigned b0, unsigned b1) {
    asm volatile(
        "mma.sync.aligned.m16n8k8.row.col.f32.tf32.tf32.f32 "
        "{%0,%1,%2,%3}, {%4,%5,%6,%7}, {%8,%9}, {%0,%1,%2,%3};"
        : "+f"(c[0]), "+f"(c[1]), "+f"(c[2]), "+f"(c[3])
        : "r"(a[0]), "r"(a[1]), "r"(a[2]), "r"(a[3]), "r"(b0), "r"(b1));
}

// ---------------- TC GEMM: C[M,256] = A[M,256] @ W[256,256], 3xTF32 split ----------------
// MODE 0: plain output (Cout or scratch csel), bias/relu per template.
// MODE 1: split epilogue: cols 0-127 -> mu (Cout), cols 128-255 -> logstd (Cout + NN*128),
//         uses g_wcat / g_bcat.
template<bool RELU, int MODE, bool BIAS>
__global__ __launch_bounds__(256)
void gemm_tc(const float* __restrict__ Ain, const float* __restrict__ Win,
             const float* __restrict__ bias_in, float* __restrict__ Cout,
             int M, int asel, int csel) {
    const float* A = (asel < 0) ? Ain : sel_buf(asel);
    const float* W = (MODE == 1) ? g_wcat : Win;
    const float* bias = (MODE == 1) ? g_bcat : bias_in;
    float* C = (MODE == 1) ? Cout : ((csel < 0) ? Cout : sel_buf(csel));

    __shared__ float As[128][36];
    __shared__ float Bs[32][136];

    int tid  = threadIdx.x;
    int lane = tid & 31, wid = tid >> 5;
    int warp_m = wid & 3, warp_n = wid >> 2;   // 4 x 2 warps: 32 rows x 64 cols each
    int bm = blockIdx.y * 128;
    int bn = blockIdx.x * 128;
    int gid = lane >> 2, tig = lane & 3;

    float acc[2][8][4];
    #pragma unroll
    for (int a = 0; a < 2; a++)
        #pragma unroll
        for (int b = 0; b < 8; b++)
            #pragma unroll
            for (int c = 0; c < 4; c++) acc[a][b][c] = 0.f;

    for (int k0 = 0; k0 < KDIM; k0 += 32) {
        // A tile: 128 x 32
        #pragma unroll
        for (int j = 0; j < 4; j++) {
            int id = tid + 256 * j;
            int r = id >> 3, c4 = (id & 7) * 4;
            float4 v = make_float4(0.f, 0.f, 0.f, 0.f);
            int gr = bm + r;
            if (gr < M) v = *(const float4*)&A[(size_t)gr * KDIM + k0 + c4];
            As[r][c4 + 0] = v.x; As[r][c4 + 1] = v.y;
            As[r][c4 + 2] = v.z; As[r][c4 + 3] = v.w;
        }
        // B tile: 32 x 128
        #pragma unroll
        for (int j = 0; j < 4; j++) {
            int id = tid + 256 * j;
            int r = id >> 5, c4 = (id & 31) * 4;
            float4 v = *(const float4*)&W[(size_t)(k0 + r) * 256 + bn + c4];
            *(float4*)&Bs[r][c4] = v;
        }
        __syncthreads();

        #pragma unroll
        for (int kk = 0; kk < 4; kk++) {
            unsigned ah[2][4], al[2][4];
            #pragma unroll
            for (int mt = 0; mt < 2; mt++) {
                int mr = warp_m * 32 + mt * 16;
                float a0 = As[mr + gid][kk * 8 + tig];
                float a1 = As[mr + gid + 8][kk * 8 + tig];
                float a2 = As[mr + gid][kk * 8 + tig + 4];
                float a3 = As[mr + gid + 8][kk * 8 + tig + 4];
                split_tf32(a0, ah[mt][0], al[mt][0]);
                split_tf32(a1, ah[mt][1], al[mt][1]);
                split_tf32(a2, ah[mt][2], al[mt][2]);
                split_tf32(a3, ah[mt][3], al[mt][3]);
            }
            #pragma unroll
            for (int nt = 0; nt < 8; nt++) {
                int nc = warp_n * 64 + nt * 8 + gid;
                float b0f = Bs[kk * 8 + tig][nc];
                float b1f = Bs[kk * 8 + tig + 4][nc];
                unsigned bh0, bl0, bh1, bl1;
                split_tf32(b0f, bh0, bl0);
                split_tf32(b1f, bh1, bl1);
                #pragma unroll
                for (int mt = 0; mt < 2; mt++) {
                    mma8(acc[mt][nt], ah[mt], bl0, bl1);   // hi*lo
                    mma8(acc[mt][nt], al[mt], bh0, bh1);   // lo*hi
                    mma8(acc[mt][nt], ah[mt], bh0, bh1);   // hi*hi
                }
            }
        }
        __syncthreads();
    }

    // epilogue
    #pragma unroll
    for (int mt = 0; mt < 2; mt++) {
        int r0 = bm + warp_m * 32 + mt * 16 + gid;
        #pragma unroll
        for (int nt = 0; nt < 8; nt++) {
            int c = bn + warp_n * 64 + nt * 8 + tig * 2;
            float v0 = acc[mt][nt][0], v1 = acc[mt][nt][1];
            float v2 = acc[mt][nt][2], v3 = acc[mt][nt][3];
            if (BIAS || MODE == 1) {
                float bb0 = bias[c], bb1 = bias[c + 1];
                v0 += bb0; v1 += bb1; v2 += bb0; v3 += bb1;
            }
            if (RELU) {
                v0 = fmaxf(v0, 0.f); v1 = fmaxf(v1, 0.f);
                v2 = fmaxf(v2, 0.f); v3 = fmaxf(v3, 0.f);
            }
            if (MODE == 0) {
                if (r0 < M)     *(float2*)&C[(size_t)r0 * 256 + c]       = make_float2(v0, v1);
                if (r0 + 8 < M) *(float2*)&C[(size_t)(r0 + 8) * 256 + c] = make_float2(v2, v3);
            } else {
                float* base = (c < 128) ? C : (C + (size_t)NN * 128);
                int cc = (c < 128) ? c : c - 128;
                if (r0 < M)     *(float2*)&base[(size_t)r0 * 128 + cc]       = make_float2(v0, v1);
                if (r0 + 8 < M) *(float2*)&base[(size_t)(r0 + 8) * 128 + cc] = make_float2(v2, v3);
            }
        }
    }
}

// ---------------- SpMM: out[c] = dinv[c]*sum val*feat[src] + dinv[c]^2*feat[c] + bias ----
__global__ __launch_bounds__(256)
void spmm_kernel(const float* __restrict__ bias, int n, int fsel, int osel) {
    const float* feat = sel_buf(fsel);
    float*       out  = sel_buf(osel);
    int warp = (blockIdx.x * blockDim.x + threadIdx.x) >> 5;
    int lane = threadIdx.x & 31;
    if (warp >= n) return;
    int beg = g_rowptr[warp];
    int end = g_rowptr[warp + 1];
    const float4* f4 = (const float4*)feat;
    float4 acc0 = make_float4(0.f, 0.f, 0.f, 0.f);
    float4 acc1 = make_float4(0.f, 0.f, 0.f, 0.f);
    for (int e = beg; e < end; e++) {
        int   r = g_src[e];
        float v = g_val[e];
        float4 a = f4[(size_t)r * 64 + lane];
        float4 b = f4[(size_t)r * 64 + 32 + lane];
        acc0.x = fmaf(v, a.x, acc0.x); acc0.y = fmaf(v, a.y, acc0.y);
        acc0.z = fmaf(v, a.z, acc0.z); acc0.w = fmaf(v, a.w, acc0.w);
        acc1.x = fmaf(v, b.x, acc1.x); acc1.y = fmaf(v, b.y, acc1.y);
        acc1.z = fmaf(v, b.z, acc1.z); acc1.w = fmaf(v, b.w, acc1.w);
    }
    float di = g_dinv[warp];
    float d2 = di * di;
    float4 s0 = f4[(size_t)warp * 64 + lane];
    float4 s1 = f4[(size_t)warp * 64 + 32 + lane];
    float4 o0, o1;
    o0.x = di * acc0.x + d2 * s0.x; o0.y = di * acc0.y + d2 * s0.y;
    o0.z = di * acc0.z + d2 * s0.z; o0.w = di * acc0.w + d2 * s0.w;
    o1.x = di * acc1.x + d2 * s1.x; o1.y = di * acc1.y + d2 * s1.y;
    o1.z = di * acc1.z + d2 * s1.z; o1.w = di * acc1.w + d2 * s1.w;
    if (bias) {
        const float4* b4 = (const float4*)bias;
        float4 c0 = b4[lane], c1 = b4[32 + lane];
        o0.x += c0.x; o0.y += c0.y; o0.z += c0.z; o0.w += c0.w;
        o1.x += c1.x; o1.y += c1.y; o1.z += c1.z; o1.w += c1.w;
    }
    float4* out4 = (float4*)out;
    out4[(size_t)warp * 64 + lane]      = o0;
    out4[(size_t)warp * 64 + 32 + lane] = o1;
}

// ---------------- launch ----------------
extern "C" void kernel_launch(void* const* d_in, const int* in_sizes, int n_in,
                              void* d_out, int out_size) {
    const float* x  = (const float*)d_in[0];
    const void*  ei = d_in[1];
    const float* ew = (const float*)d_in[2];
    const float* wd = (const float*)d_in[3];
    const float* bd = (const float*)d_in[4];
    const float* we = (const float*)d_in[5];
    const float* be = (const float*)d_in[6];
    const float* wm = (const float*)d_in[7];
    const float* bmu = (const float*)d_in[8];
    const float* wl = (const float*)d_in[9];
    const float* bl = (const float*)d_in[10];
    float* out = (float*)d_out;

    const int n = NN;
    const int e = EE;

    detect_kernel<<<1, 1024>>>((const int*)ei, 2 * e);
    init_kernel<<<(n + 255) / 256, 256>>>(n);
    edge_pass<<<(e + 255) / 256, 256>>>(ei, ew, e);
    dinv_kernel<<<(n + 255) / 256, 256>>>(n);
    scan_kernel<<<1, 1024>>>(n);
    scatter_kernel<<<(e + 255) / 256, 256>>>(ei, ew, e);
    concat_w<<<(256 * 256 + 255) / 256, 256>>>(wm, wl, bmu, bl);

    dim3 grid(2, (n + 127) / 128);

    // h0 = relu(x @ Wd + bd)  -> g_b0
    gemm_tc<true, 0, true><<<grid, 256>>>(x, wd, bd, nullptr, n, -1, 0);
    // t = h0 @ We             -> g_b1
    gemm_tc<false, 0, false><<<grid, 256>>>(nullptr, we, nullptr, nullptr, n, 0, 1);
    // h1 = A_norm @ t + be    -> g_b2
    int spmm_blocks = (n * 32 + 255) / 256;
    spmm_kernel<<<spmm_blocks, 256>>>(be, n, 1, 2);
    // z = A_norm @ h1         -> g_b0
    spmm_kernel<<<spmm_blocks, 256>>>(nullptr, n, 2, 0);
    // [mu | logstd] = z @ [Wmu|Wls] + [bmu|bls], split epilogue
    gemm_tc<false, 1, true><<<grid, 256>>>(nullptr, nullptr, nullptr, out, n, 0, 0);
}

// round 5
// speedup vs baseline: 1.5448x; 1.1976x over previous
#include <cuda_runtime.h>

#define NN   100000
#define EE   1600000
#define KDIM 256

// ---------------- scratch (device globals) ----------------
__device__ float g_b0[(size_t)NN * KDIM];   // h0, later reused as z
__device__ float g_b1[(size_t)NN * KDIM];   // t = h0 @ W_enc
__device__ float g_b2[(size_t)NN * KDIM];   // h1
__device__ float g_wcat[256 * 256];         // [Wmu | Wlogstd]
__device__ float g_bcat[256];
__device__ float g_deg[NN];
__device__ float g_dinv[NN];
__device__ int   g_cnt[NN];
__device__ int   g_rowptr[NN + 1];
__device__ int   g_cursor[NN];
__device__ int   g_src[EE];
__device__ float g_val[EE];
__device__ int   g_is64;

// ---------------- edge-index dtype detection ----------------
__global__ void detect_kernel(const int* __restrict__ ei32, int n_int32) {
    __shared__ int any;
    if (threadIdx.x == 0) any = 0;
    __syncthreads();
    for (int i = threadIdx.x; i < 4096; i += blockDim.x) {
        int pos = 2 * i + 1;
        if (pos < n_int32 && ei32[pos] != 0) any = 1;
    }
    __syncthreads();
    if (threadIdx.x == 0) g_is64 = (any == 0) ? 1 : 0;
}

__device__ __forceinline__ int load_idx(const void* ei, int e, int part, int i) {
    if (g_is64) return (int)((const long long*)ei)[(size_t)part * e + i];
    return ((const int*)ei)[(size_t)part * e + i];
}

// ---------------- graph preprocessing ----------------
__global__ void init_kernel(int n) {
    int i = blockIdx.x * blockDim.x + threadIdx.x;
    if (i < n) { g_deg[i] = 1.0f; g_cnt[i] = 0; }
}

__global__ void edge_pass(const void* __restrict__ ei,
                          const float* __restrict__ ew, int e) {
    int i = blockIdx.x * blockDim.x + threadIdx.x;
    if (i >= e) return;
    int c = load_idx(ei, e, 1, i);
    if ((unsigned)c >= NN) return;
    atomicAdd(&g_deg[c], ew[i]);
    atomicAdd(&g_cnt[c], 1);
}

__global__ void dinv_kernel(int n) {
    int i = blockIdx.x * blockDim.x + threadIdx.x;
    if (i < n) g_dinv[i] = rsqrtf(g_deg[i]);
}

__global__ void scan_kernel(int n) {
    __shared__ int part[1024];
    int tid = threadIdx.x;
    int chunk = (n + 1023) >> 10;
    int beg = tid * chunk;
    int end = beg + chunk; if (end > n) end = n;
    int s = 0;
    for (int i = beg; i < end; i++) s += g_cnt[i];
    part[tid] = s;
    __syncthreads();
    for (int off = 1; off < 1024; off <<= 1) {
        int v = (tid >= off) ? part[tid - off] : 0;
        __syncthreads();
        part[tid] += v;
        __syncthreads();
    }
    int run = (tid > 0) ? part[tid - 1] : 0;
    for (int i = beg; i < end; i++) {
        g_rowptr[i] = run; g_cursor[i] = run; run += g_cnt[i];
    }
    if (tid == 1023) g_rowptr[n] = part[1023];
}

__global__ void scatter_kernel(const void* __restrict__ ei,
                               const float* __restrict__ ew, int e) {
    int i = blockIdx.x * blockDim.x + threadIdx.x;
    if (i >= e) return;
    int r = load_idx(ei, e, 0, i);
    int c = load_idx(ei, e, 1, i);
    if ((unsigned)r >= NN || (unsigned)c >= NN) return;
    int pos = atomicAdd(&g_cursor[c], 1);
    g_src[pos] = r;
    g_val[pos] = ew[i] * g_dinv[r];
}

__global__ void concat_w(const float* __restrict__ wm, const float* __restrict__ wl,
                         const float* __restrict__ bm_, const float* __restrict__ bl_) {
    int i = blockIdx.x * blockDim.x + threadIdx.x;
    if (i < 256 * 256) {
        int k = i >> 8, nn = i & 255;
        g_wcat[i] = (nn < 128) ? wm[k * 128 + nn] : wl[k * 128 + nn - 128];
    }
    if (i < 256) g_bcat[i] = (i < 128) ? bm_[i] : bl_[i - 128];
}

__device__ __forceinline__ float* sel_buf(int s) {
    return s == 0 ? g_b0 : (s == 1 ? g_b1 : g_b2);
}

// ---------------- bf16 split helpers ----------------
// Pack two k-consecutive fp32 into bf16x2 (x0 -> low 16, x1 -> high 16),
// and the residuals into a second bf16x2. 3-term product error ~2^-18.
__device__ __forceinline__ void split_pair(float x0, float x1,
                                           unsigned& hi, unsigned& lo) {
    unsigned h;
    asm("cvt.rn.bf16x2.f32 %0, %1, %2;" : "=r"(h) : "f"(x1), "f"(x0));
    float h0 = __uint_as_float(h << 16);
    float h1 = __uint_as_float(h & 0xffff0000u);
    float r0 = x0 - h0, r1 = x1 - h1;
    unsigned l;
    asm("cvt.rn.bf16x2.f32 %0, %1, %2;" : "=r"(l) : "f"(r1), "f"(r0));
    hi = h; lo = l;
}

__device__ __forceinline__ void mma16(float c[4], const unsigned a[4],
                                      unsigned b0, unsigned b1) {
    asm volatile(
        "mma.sync.aligned.m16n8k16.row.col.f32.bf16.bf16.f32 "
        "{%0,%1,%2,%3}, {%4,%5,%6,%7}, {%8,%9}, {%0,%1,%2,%3};"
        : "+f"(c[0]), "+f"(c[1]), "+f"(c[2]), "+f"(c[3])
        : "r"(a[0]), "r"(a[1]), "r"(a[2]), "r"(a[3]), "r"(b0), "r"(b1));
}

// ---------------- TC GEMM: C[M,256] = A[M,256] @ W[256,256], 3-term bf16 split ----------------
// MODE 0: plain output; MODE 1: split epilogue mu/logstd using g_wcat/g_bcat.
template<bool RELU, int MODE, bool BIAS>
__global__ __launch_bounds__(256)
void gemm_tc(const float* __restrict__ Ain, const float* __restrict__ Win,
             const float* __restrict__ bias_in, float* __restrict__ Cout,
             int M, int asel, int csel) {
    const float* A = (asel < 0) ? Ain : sel_buf(asel);
    const float* W = (MODE == 1) ? g_wcat : Win;
    const float* bias = (MODE == 1) ? g_bcat : bias_in;
    float* C = (MODE == 1) ? Cout : ((csel < 0) ? Cout : sel_buf(csel));

    __shared__ float As[128][36];
    __shared__ float Bs[32][136];

    int tid  = threadIdx.x;
    int lane = tid & 31, wid = tid >> 5;
    int warp_m = wid & 3, warp_n = wid >> 2;   // 4 x 2 warps: 32 rows x 64 cols each
    int bm = blockIdx.y * 128;
    int bn = blockIdx.x * 128;
    int gid = lane >> 2, tig = lane & 3;       // group-of-4 id, thread-in-group

    float acc[2][8][4];
    #pragma unroll
    for (int a = 0; a < 2; a++)
        #pragma unroll
        for (int b = 0; b < 8; b++)
            #pragma unroll
            for (int c = 0; c < 4; c++) acc[a][b][c] = 0.f;

    for (int k0 = 0; k0 < KDIM; k0 += 32) {
        // A tile: 128 x 32
        #pragma unroll
        for (int j = 0; j < 4; j++) {
            int id = tid + 256 * j;
            int r = id >> 3, c4 = (id & 7) * 4;
            float4 v = make_float4(0.f, 0.f, 0.f, 0.f);
            int gr = bm + r;
            if (gr < M) v = *(const float4*)&A[(size_t)gr * KDIM + k0 + c4];
            As[r][c4 + 0] = v.x; As[r][c4 + 1] = v.y;
            As[r][c4 + 2] = v.z; As[r][c4 + 3] = v.w;
        }
        // B tile: 32 x 128
        #pragma unroll
        for (int j = 0; j < 4; j++) {
            int id = tid + 256 * j;
            int r = id >> 5, c4 = (id & 31) * 4;
            float4 v = *(const float4*)&W[(size_t)(k0 + r) * 256 + bn + c4];
            *(float4*)&Bs[r][c4] = v;
        }
        __syncthreads();

        #pragma unroll
        for (int kk = 0; kk < 2; kk++) {          // two k16 sub-chunks
            int kb = kk * 16;
            // A fragments (m16n8k16 row-major): regs hold k-pairs
            unsigned ah[2][4], al[2][4];
            #pragma unroll
            for (int mt = 0; mt < 2; mt++) {
                int mr = warp_m * 32 + mt * 16;
                float2 p0 = *(const float2*)&As[mr + gid][kb + 2 * tig];
                float2 p1 = *(const float2*)&As[mr + gid + 8][kb + 2 * tig];
                float2 p2 = *(const float2*)&As[mr + gid][kb + 8 + 2 * tig];
                float2 p3 = *(const float2*)&As[mr + gid + 8][kb + 8 + 2 * tig];
                split_pair(p0.x, p0.y, ah[mt][0], al[mt][0]);
                split_pair(p1.x, p1.y, ah[mt][1], al[mt][1]);
                split_pair(p2.x, p2.y, ah[mt][2], al[mt][2]);
                split_pair(p3.x, p3.y, ah[mt][3], al[mt][3]);
            }
            #pragma unroll
            for (int nt = 0; nt < 8; nt++) {
                int nc = warp_n * 64 + nt * 8 + gid;
                float b00 = Bs[kb + 2 * tig][nc];
                float b01 = Bs[kb + 2 * tig + 1][nc];
                float b10 = Bs[kb + 8 + 2 * tig][nc];
                float b11 = Bs[kb + 8 + 2 * tig + 1][nc];
                unsigned bh0, bl0, bh1, bl1;
                split_pair(b00, b01, bh0, bl0);
                split_pair(b10, b11, bh1, bl1);
                #pragma unroll
                for (int mt = 0; mt < 2; mt++) {
                    mma16(acc[mt][nt], ah[mt], bl0, bl1);   // hi*lo
                    mma16(acc[mt][nt], al[mt], bh0, bh1);   // lo*hi
                    mma16(acc[mt][nt], ah[mt], bh0, bh1);   // hi*hi
                }
            }
        }
        __syncthreads();
    }

    // epilogue (same c-fragment layout as m16n8k8)
    #pragma unroll
    for (int mt = 0; mt < 2; mt++) {
        int r0 = bm + warp_m * 32 + mt * 16 + gid;
        #pragma unroll
        for (int nt = 0; nt < 8; nt++) {
            int c = bn + warp_n * 64 + nt * 8 + tig * 2;
            float v0 = acc[mt][nt][0], v1 = acc[mt][nt][1];
            float v2 = acc[mt][nt][2], v3 = acc[mt][nt][3];
            if (BIAS || MODE == 1) {
                float bb0 = bias[c], bb1 = bias[c + 1];
                v0 += bb0; v1 += bb1; v2 += bb0; v3 += bb1;
            }
            if (RELU) {
                v0 = fmaxf(v0, 0.f); v1 = fmaxf(v1, 0.f);
                v2 = fmaxf(v2, 0.f); v3 = fmaxf(v3, 0.f);
            }
            if (MODE == 0) {
                if (r0 < M)     *(float2*)&C[(size_t)r0 * 256 + c]       = make_float2(v0, v1);
                if (r0 + 8 < M) *(float2*)&C[(size_t)(r0 + 8) * 256 + c] = make_float2(v2, v3);
            } else {
                float* base = (c < 128) ? C : (C + (size_t)NN * 128);
                int cc = (c < 128) ? c : c - 128;
                if (r0 < M)     *(float2*)&base[(size_t)r0 * 128 + cc]       = make_float2(v0, v1);
                if (r0 + 8 < M) *(float2*)&base[(size_t)(r0 + 8) * 128 + cc] = make_float2(v2, v3);
            }
        }
    }
}

// ---------------- SpMM: out[c] = dinv[c]*sum val*feat[src] + dinv[c]^2*feat[c] + bias ----
__global__ __launch_bounds__(256)
void spmm_kernel(const float* __restrict__ bias, int n, int fsel, int osel) {
    const float* feat = sel_buf(fsel);
    float*       out  = sel_buf(osel);
    int warp = (blockIdx.x * blockDim.x + threadIdx.x) >> 5;
    int lane = threadIdx.x & 31;
    if (warp >= n) return;
    int beg = g_rowptr[warp];
    int end = g_rowptr[warp + 1];
    const float4* f4 = (const float4*)feat;
    float4 acc0 = make_float4(0.f, 0.f, 0.f, 0.f);
    float4 acc1 = make_float4(0.f, 0.f, 0.f, 0.f);
    for (int e = beg; e < end; e++) {
        int   r = g_src[e];
        float v = g_val[e];
        float4 a = f4[(size_t)r * 64 + lane];
        float4 b = f4[(size_t)r * 64 + 32 + lane];
        acc0.x = fmaf(v, a.x, acc0.x); acc0.y = fmaf(v, a.y, acc0.y);
        acc0.z = fmaf(v, a.z, acc0.z); acc0.w = fmaf(v, a.w, acc0.w);
        acc1.x = fmaf(v, b.x, acc1.x); acc1.y = fmaf(v, b.y, acc1.y);
        acc1.z = fmaf(v, b.z, acc1.z); acc1.w = fmaf(v, b.w, acc1.w);
    }
    float di = g_dinv[warp];
    float d2 = di * di;
    float4 s0 = f4[(size_t)warp * 64 + lane];
    float4 s1 = f4[(size_t)warp * 64 + 32 + lane];
    float4 o0, o1;
    o0.x = di * acc0.x + d2 * s0.x; o0.y = di * acc0.y + d2 * s0.y;
    o0.z = di * acc0.z + d2 * s0.z; o0.w = di * acc0.w + d2 * s0.w;
    o1.x = di * acc1.x + d2 * s1.x; o1.y = di * acc1.y + d2 * s1.y;
    o1.z = di * acc1.z + d2 * s1.z; o1.w = di * acc1.w + d2 * s1.w;
    if (bias) {
        const float4* b4 = (const float4*)bias;
        float4 c0 = b4[lane], c1 = b4[32 + lane];
        o0.x += c0.x; o0.y += c0.y; o0.z += c0.z; o0.w += c0.w;
        o1.x += c1.x; o1.y += c1.y; o1.z += c1.z; o1.w += c1.w;
    }
    float4* out4 = (float4*)out;
    out4[(size_t)warp * 64 + lane]      = o0;
    out4[(size_t)warp * 64 + 32 + lane] = o1;
}

// ---------------- launch ----------------
extern "C" void kernel_launch(void* const* d_in, const int* in_sizes, int n_in,
                              void* d_out, int out_size) {
    const float* x  = (const float*)d_in[0];
    const void*  ei = d_in[1];
    const float* ew = (const float*)d_in[2];
    const float* wd = (const float*)d_in[3];
    const float* bd = (const float*)d_in[4];
    const float* we = (const float*)d_in[5];
    const float* be = (const float*)d_in[6];
    const float* wm = (const float*)d_in[7];
    const float* bmu = (const float*)d_in[8];
    const float* wl = (const float*)d_in[9];
    const float* bl = (const float*)d_in[10];
    float* out = (float*)d_out;

    const int n = NN;
    const int e = EE;

    detect_kernel<<<1, 1024>>>((const int*)ei, 2 * e);
    init_kernel<<<(n + 255) / 256, 256>>>(n);
    edge_pass<<<(e + 255) / 256, 256>>>(ei, ew, e);
    dinv_kernel<<<(n + 255) / 256, 256>>>(n);
    scan_kernel<<<1, 1024>>>(n);
    scatter_kernel<<<(e + 255) / 256, 256>>>(ei, ew, e);
    concat_w<<<(256 * 256 + 255) / 256, 256>>>(wm, wl, bmu, bl);

    dim3 grid(2, (n + 127) / 128);

    // h0 = relu(x @ Wd + bd)  -> g_b0
    gemm_tc<true, 0, true><<<grid, 256>>>(x, wd, bd, nullptr, n, -1, 0);
    // t = h0 @ We             -> g_b1
    gemm_tc<false, 0, false><<<grid, 256>>>(nullptr, we, nullptr, nullptr, n, 0, 1);
    // h1 = A_norm @ t + be    -> g_b2
    int spmm_blocks = (n * 32 + 255) / 256;
    spmm_kernel<<<spmm_blocks, 256>>>(be, n, 1, 2);
    // z = A_norm @ h1         -> g_b0
    spmm_kernel<<<spmm_blocks, 256>>>(nullptr, n, 2, 0);
    // [mu | logstd] = z @ [Wmu|Wls] + [bmu|bls], split epilogue
    gemm_tc<false, 1, true><<<grid, 256>>>(nullptr, nullptr, nullptr, out, n, 0, 0);
}